// round 4
// baseline (speedup 1.0000x reference)
#include <cuda_runtime.h>
#include <cuda_fp16.h>
#include <math.h>

#define BATCH 16
#define CH 64
#define HLO 80
#define WLO 80
#define HWLO (HLO*WLO)
#define HHI 160
#define WHI 160

typedef unsigned long long ull;

// Scratch
__device__ __half g_zh[BATCH * HWLO * CH];  // conv(x), fp16, channel-last [b][hw][c]
__device__ float  g_om[BATCH * HWLO * 12];  // [b][hw][ ox(4), oy(4), sig(mask)(4) ]

struct alignas(16) H8 { __half2 h[4]; };

// ---- packed f32x2 helpers -------------------------------------------------
__device__ __forceinline__ ull fma2(ull a, ull b, ull c) {
    ull d;
    asm("fma.rn.f32x2 %0, %1, %2, %3;" : "=l"(d) : "l"(a), "l"(b), "l"(c));
    return d;
}
__device__ __forceinline__ ull packdup(float w) {
    ull d; unsigned u = __float_as_uint(w);
    asm("mov.b64 %0, {%1, %2};" : "=l"(d) : "r"(u), "r"(u));
    return d;
}
__device__ __forceinline__ float2 u2f2(ull v) {
    float2 r;
    asm("mov.b64 {%0, %1}, %2;" : "=f"(r.x), "=f"(r.y) : "l"(v));
    return r;
}

// ---------------------------------------------------------------------------
// Kernel 1: fused 1x1 convs at LOW resolution, f32x2 packed math.
// 320 threads, tile 128 px x 80 outputs, K=64 smem-resident.
// Microtile 8 out x 4 px (2 f32x2 pairs) -> 32 acc regs, no spills,
// 2 blocks/SM = 20 warps/SM.
// ---------------------------------------------------------------------------
__global__ __launch_bounds__(320, 2) void conv_lowres_kernel(
    const float* __restrict__ x,
    const float* __restrict__ conv_w,
    const float* __restrict__ offset_w,
    const float* __restrict__ offset_b,
    const float* __restrict__ mask_w,
    const float* __restrict__ mask_b)
{
    extern __shared__ float smem[];
    float (*Xs)[128] = (float(*)[128])smem;              // [c][pix]  32KB
    float (*Wt)[80]  = (float(*)[80])(smem + 64 * 128);  // [c][o]    20KB

    const int b = blockIdx.y;
    const int pix0 = blockIdx.x * 128;
    const int t = threadIdx.x;

    // Weights transposed
    for (int idx = t; idx < 64 * 80; idx += 320) {
        int c = idx / 80, o = idx % 80;
        float v;
        if (o < 64)      v = conv_w[o * 64 + c];
        else if (o < 72) v = offset_w[(o - 64) * 64 + c];
        else if (o < 76) v = mask_w[(o - 72) * 64 + c];
        else             v = 0.f;
        Wt[c][o] = v;
    }
    // Full X tile [64 c][128 px] as float4
    const float* xb = x + ((size_t)b * CH) * HWLO + pix0;
    for (int idx = t; idx < 64 * 32; idx += 320) {
        int c = idx >> 5, p4 = idx & 31;
        *reinterpret_cast<float4*>(&Xs[c][p4 * 4]) =
            *reinterpret_cast<const float4*>(&xb[c * HWLO + p4 * 4]);
    }
    __syncthreads();

    const int tx = t % 10;         // ob = tx*8
    const int ty = t / 10;         // pb = ty*4   (ty 0..31)
    const int ob = tx * 8, pb = ty * 4;

    ull acc[8][2];
    #pragma unroll
    for (int o = 0; o < 8; o++) { acc[o][0] = 0ull; acc[o][1] = 0ull; }

    #pragma unroll 8
    for (int c = 0; c < 64; c++) {
        ulonglong2 a = *reinterpret_cast<const ulonglong2*>(&Xs[c][pb]);
        float4 w0 = *reinterpret_cast<const float4*>(&Wt[c][ob]);
        float4 w1 = *reinterpret_cast<const float4*>(&Wt[c][ob + 4]);
        ull wd[8] = {packdup(w0.x), packdup(w0.y), packdup(w0.z), packdup(w0.w),
                     packdup(w1.x), packdup(w1.y), packdup(w1.z), packdup(w1.w)};
        #pragma unroll
        for (int o = 0; o < 8; o++) {
            acc[o][0] = fma2(a.x, wd[o], acc[o][0]);
            acc[o][1] = fma2(a.y, wd[o], acc[o][1]);
        }
    }

    const int pixbase = b * HWLO + pix0 + pb;

    if (ob < 64) {
        #pragma unroll
        for (int i = 0; i < 4; i++) {
            float f[8];
            #pragma unroll
            for (int o = 0; o < 8; o++) {
                float2 v = u2f2(acc[o][i >> 1]);
                f[o] = (i & 1) ? v.y : v.x;
            }
            H8 hv;
            hv.h[0] = __floats2half2_rn(f[0], f[1]);
            hv.h[1] = __floats2half2_rn(f[2], f[3]);
            hv.h[2] = __floats2half2_rn(f[4], f[5]);
            hv.h[3] = __floats2half2_rn(f[6], f[7]);
            *reinterpret_cast<H8*>(&g_zh[(size_t)(pixbase + i) * CH + ob]) = hv;
        }
    } else if (ob == 64) {
        #pragma unroll
        for (int i = 0; i < 4; i++) {
            float f[8];
            #pragma unroll
            for (int o = 0; o < 8; o++) {
                float2 v = u2f2(acc[o][i >> 1]);
                f[o] = ((i & 1) ? v.y : v.x) + offset_b[o];
            }
            float* dst = &g_om[(size_t)(pixbase + i) * 12];
            *reinterpret_cast<float4*>(dst)     = make_float4(f[0], f[1], f[2], f[3]);
            *reinterpret_cast<float4*>(dst + 4) = make_float4(f[4], f[5], f[6], f[7]);
        }
    } else { // ob == 72: mask outputs 72..75
        #pragma unroll
        for (int i = 0; i < 4; i++) {
            float f[4];
            #pragma unroll
            for (int o = 0; o < 4; o++) {
                float2 v = u2f2(acc[o][i >> 1]);
                float m = ((i & 1) ? v.y : v.x) + mask_b[o];
                f[o] = __fdividef(1.f, 1.f + __expf(-m));
            }
            *reinterpret_cast<float4*>(&g_om[(size_t)(pixbase + i) * 12 + 8]) =
                make_float4(f[0], f[1], f[2], f[3]);
        }
    }
}

// ---------------------------------------------------------------------------
// Composite (grid_sample o upsample) weights for one dimension.
// ---------------------------------------------------------------------------
__device__ __forceinline__ void dim_weights(float coord, float w[3], int& rbase)
{
    w[0] = w[1] = w[2] = 0.f;
    int c0 = (int)floorf(coord);
    float f = coord - (float)c0;
    float cw0 = 1.f - f, cw1 = f;
    rbase = -1;
    #pragma unroll
    for (int k = 0; k < 2; k++) {
        int h = c0 + k;
        float cw = k ? cw1 : cw0;
        if (h < 0 || h >= HHI) continue;
        float cl = 0.5f * (float)h - 0.25f;
        cl = fminf(fmaxf(cl, 0.f), (float)(HLO - 1));
        int i0 = (int)cl;
        float fw = cl - (float)i0;
        int i1 = min(i0 + 1, HLO - 1);
        if (rbase < 0) rbase = i0;
        int d = i0 - rbase;
        w[d]             += cw * (1.f - fw);
        w[d + (i1 - i0)] += cw * fw;
    }
    if (rbase < 0) rbase = 0;
}

// ---------------------------------------------------------------------------
// Kernel 2: fused sampler, fp16 z, half2 row accumulation.
// 32 output pixels x 64 channels per block; thread = 1 px x 8 ch.
// Row sums (3 taps, wx weights) in half2 HFMA2; rows combined in fp32 (wy).
// ---------------------------------------------------------------------------
__global__ __launch_bounds__(256) void sample_kernel(
    float* __restrict__ out,
    const float* __restrict__ bn_gamma,
    const float* __restrict__ bn_beta,
    const float* __restrict__ bn_mean,
    const float* __restrict__ bn_var)
{
    __shared__ float   s_wy[32][3];
    __shared__ __half2 s_wxh[32][3];
    __shared__ int     s_ro[32][3];
    __shared__ int     s_co[32][3];
    __shared__ float   s_m[32];
    __shared__ float   s_bns[64];
    __shared__ float   s_bnb[64];
    __shared__ float   s_out[64 * 33];

    const int t = threadIdx.x;
    const int b = blockIdx.z;
    const int hs = blockIdx.y;
    const int ws0 = blockIdx.x * 32;

    if (t < 64) {
        float sc = bn_gamma[t] * rsqrtf(bn_var[t] + 1e-5f);
        s_bns[t] = sc;
        s_bnb[t] = bn_beta[t] - bn_mean[t] * sc;
    }
    if (t < 32) {
        int ws = ws0 + t;
        int h = hs >> 1, w = ws >> 1;
        int p = ((hs & 1) << 1) | (ws & 1);
        const float* om = g_om + ((size_t)(b * HWLO + h * WLO + w) * 12);
        float ox = om[p];
        float oy = om[4 + p];
        s_m[t] = om[8 + p];
        float gx = -1.f + (float)ws * (2.f / (float)(WHI - 1)) + ox;
        float gy = -1.f + (float)hs * (2.f / (float)(HHI - 1)) + oy;
        float ix = ((gx + 1.f) * (float)WHI - 1.f) * 0.5f;
        float iy = ((gy + 1.f) * (float)HHI - 1.f) * 0.5f;
        float wy[3], wx[3]; int ry, rx;
        dim_weights(iy, wy, ry);
        dim_weights(ix, wx, rx);
        #pragma unroll
        for (int i = 0; i < 3; i++) {
            s_wy[t][i]  = wy[i];
            s_wxh[t][i] = __float2half2_rn(wx[i]);
            s_ro[t][i]  = min(ry + i, HLO - 1) * (WLO * CH);
            s_co[t][i]  = min(rx + i, WLO - 1) * CH;
        }
    }
    __syncthreads();

    const int px = t >> 3;             // 0..31
    const int c0 = (t & 7) * 8;        // 8 channels per thread
    const __half* zb = g_zh + (size_t)b * HWLO * CH + c0;

    float acc[8];
    #pragma unroll
    for (int j = 0; j < 8; j++) acc[j] = 0.f;

    #pragma unroll
    for (int i = 0; i < 3; i++) {
        const __half* zrow = zb + s_ro[px][i];
        __half2 r0 = __float2half2_rn(0.f), r1 = r0, r2 = r0, r3 = r0;
        #pragma unroll
        for (int j = 0; j < 3; j++) {
            uint4 v = *reinterpret_cast<const uint4*>(zrow + s_co[px][j]);
            __half2 wj = s_wxh[px][j];
            r0 = __hfma2(*reinterpret_cast<const __half2*>(&v.x), wj, r0);
            r1 = __hfma2(*reinterpret_cast<const __half2*>(&v.y), wj, r1);
            r2 = __hfma2(*reinterpret_cast<const __half2*>(&v.z), wj, r2);
            r3 = __hfma2(*reinterpret_cast<const __half2*>(&v.w), wj, r3);
        }
        float wyi = s_wy[px][i];
        float2 f0 = __half22float2(r0);
        float2 f1 = __half22float2(r1);
        float2 f2 = __half22float2(r2);
        float2 f3 = __half22float2(r3);
        acc[0] = fmaf(wyi, f0.x, acc[0]);
        acc[1] = fmaf(wyi, f0.y, acc[1]);
        acc[2] = fmaf(wyi, f1.x, acc[2]);
        acc[3] = fmaf(wyi, f1.y, acc[3]);
        acc[4] = fmaf(wyi, f2.x, acc[4]);
        acc[5] = fmaf(wyi, f2.y, acc[5]);
        acc[6] = fmaf(wyi, f3.x, acc[6]);
        acc[7] = fmaf(wyi, f3.y, acc[7]);
    }

    const float m = s_m[px];
    #pragma unroll
    for (int j = 0; j < 8; j++) {
        int o = c0 + j;
        float y = acc[j] * (m * s_bns[o]) + s_bnb[o];
        y = y * __fdividef(1.f, 1.f + __expf(-y));   // SiLU
        s_out[o * 33 + px] = y;
    }
    __syncthreads();

    // Coalesced NCHW writes
    #pragma unroll
    for (int r = 0; r < 2; r++) {
        int idx = t + r * 256;
        int o = idx >> 3, px0 = (idx & 7) * 4;
        float4 v = make_float4(s_out[o * 33 + px0],     s_out[o * 33 + px0 + 1],
                               s_out[o * 33 + px0 + 2], s_out[o * 33 + px0 + 3]);
        *reinterpret_cast<float4*>(
            out + (((size_t)(b * CH + o)) * HHI + hs) * WHI + ws0 + px0) = v;
    }
}

// ---------------------------------------------------------------------------
extern "C" void kernel_launch(void* const* d_in, const int* in_sizes, int n_in,
                              void* d_out, int out_size)
{
    const float* x        = (const float*)d_in[0];
    const float* offset_w = (const float*)d_in[1];
    const float* offset_b = (const float*)d_in[2];
    const float* mask_w   = (const float*)d_in[3];
    const float* mask_b   = (const float*)d_in[4];
    const float* conv_w   = (const float*)d_in[5];
    const float* bn_gamma = (const float*)d_in[6];
    const float* bn_beta  = (const float*)d_in[7];
    const float* bn_mean  = (const float*)d_in[8];
    const float* bn_var   = (const float*)d_in[9];
    float* out = (float*)d_out;

    const int conv_smem = (64 * 128 + 64 * 80) * sizeof(float);  // 53248
    cudaFuncSetAttribute(conv_lowres_kernel,
                         cudaFuncAttributeMaxDynamicSharedMemorySize, conv_smem);

    conv_lowres_kernel<<<dim3(HWLO / 128, BATCH), 320, conv_smem>>>(
        x, conv_w, offset_w, offset_b, mask_w, mask_b);
    sample_kernel<<<dim3(WHI / 32, HHI, BATCH), 256>>>(
        out, bn_gamma, bn_beta, bn_mean, bn_var);
}